// round 9
// baseline (speedup 1.0000x reference)
#include <cuda_runtime.h>
#include <cstdint>

// ---------------------------------------------------------------------------
// VQ nearest-code quantization + cosine score — 1xTF32 mma.sync + exact refine.
// R9: permuted fragment staging (LDS.128), 4x-parallel refine w/ atomicMin merge.
// ---------------------------------------------------------------------------

namespace {
constexpr int kC    = 256;
constexpr int kNE   = 1024;
constexpr int kCHW  = 256 * 1024;
constexpr int kNTok = 64 * 1024;
constexpr int kZQ   = kNTok * kC;
constexpr int kCOS  = 64 * 32 * 256;
constexpr int kOffCos  = kZQ;
constexpr int kOffIdxG = kZQ + kCOS;
constexpr int kOffIdxZ = kOffIdxG + kNTok;
constexpr int kFlagCap = 2 * kNTok;
constexpr float kMargin = 2e-3f;          // ~10 sigma of tf32 dot error
}

__device__ float g_codeNorm[kNE];
__device__ float g_tokNorm[2 * kNTok];
__device__ int   g_idx[2 * kNTok];
__device__ float g_blimb[1024 * 256];             // tf32 codebook, k-chunk permuted
__device__ float g_alimb[2ll * 65536 * 256];      // tf32 tokens, token-major, permuted
__device__ int   g_flagCount;
__device__ int   g_flagList[kFlagCap];
__device__ unsigned long long g_refKey[kFlagCap];

// ------------------------------ helpers ------------------------------------
__device__ __forceinline__ uint32_t smem_u32(const void* p) {
    uint32_t a;
    asm("{ .reg .u64 t; cvta.to.shared.u64 t, %1; cvt.u32.u64 %0, t; }"
        : "=r"(a) : "l"(p));
    return a;
}
__device__ __forceinline__ float to_tf32(float x) {
    float r; asm("cvt.rna.tf32.f32 %0, %1;" : "=f"(r) : "f"(x)); return r;
}
__device__ __forceinline__ void cp16(uint32_t dst, const float* src) {
    asm volatile("cp.async.cg.shared.global [%0], [%1], 16;"
                 :: "r"(dst), "l"(src) : "memory");
}
#define CP_COMMIT() asm volatile("cp.async.commit_group;" ::: "memory")
#define CP_WAIT1()  asm volatile("cp.async.wait_group 1;" ::: "memory")
#define CP_WAIT0()  asm volatile("cp.async.wait_group 0;" ::: "memory")

#define MMA(d, a0, a1, a2, a3, b0, b1) \
    asm volatile("mma.sync.aligned.m16n8k8.row.col.f32.tf32.tf32.f32 " \
        "{%0,%1,%2,%3}, {%4,%5,%6,%7}, {%8,%9}, {%0,%1,%2,%3};" \
        : "+f"((d)[0]), "+f"((d)[1]), "+f"((d)[2]), "+f"((d)[3]) \
        : "r"(a0), "r"(a1), "r"(a2), "r"(a3), "r"(b0), "r"(b1))

// chunk-local fragment permutation: k (0..31) -> p
__host__ __device__ __forceinline__ int kperm(int k) {
    return (k & 3) * 8 + (k >> 3) * 2 + ((k >> 2) & 1);
}

// SMEM: buffer b (b=0..2) at b*36864: A [128][36]f @0, B [128][36]f @18432
#define BUF     36864
#define SM_B    18432
#define SM_NORM 110592
#define SM_RV   111104
#define SM_RI   112128
#define SM_RV2  113152
#define SMEM_BYTES 114176

// ---------------------------------------------------------------------------
// #1: codebook norms + tf32 rounding (permuted), flag reset.
__global__ void prep_cb_kernel(const float* __restrict__ cb) {
    int j = blockIdx.x * blockDim.x + threadIdx.x;
    if (j == 0) g_flagCount = 0;
    if (j >= kNE) return;
    const float* r = cb + j * kC;
    float s = 0.f;
    for (int c = 0; c < kC; ++c) {
        float v = r[c];
        s = fmaf(v, v, s);
        g_blimb[j * kC + (c & ~31) + kperm(c & 31)] = to_tf32(v);
    }
    g_codeNorm[j] = s;
}

// #2: exact token norms (ascending-c fmaf chain, matches refine).
__global__ void prep_tok_kernel(const float* __restrict__ z,
                                const float* __restrict__ gt) {
    int t = blockIdx.x * blockDim.x + threadIdx.x;
    if (t >= 2 * kNTok) return;
    const float* src = (t < kNTok) ? z : gt;
    int tl = t & (kNTok - 1);
    const float* p = src + (tl >> 10) * kCHW + (tl & 1023);
    float s = 0.f;
    for (int c = 0; c < kC; ++c) { float a = p[c * 1024]; s = fmaf(a, a, s); }
    g_tokNorm[t] = s;
}

// #3: transpose+round z/gt into permuted token-major staging.
__global__ void alimb_kernel(const float* __restrict__ z,
                             const float* __restrict__ gt) {
    __shared__ float s[32][33];
    int blk = blockIdx.x;                 // 2 * 64 * 32 * 8
    int tensor = blk >> 14;
    int b   = (blk >> 8) & 63;
    int hwT = (blk >> 3) & 31;
    int cT  = blk & 7;
    const float* src = tensor ? gt : z;
    int tid = threadIdx.x;
#pragma unroll
    for (int u = 0; u < 4; u++) {
        int cl = (tid >> 5) + u * 8, hw = tid & 31;
        s[cl][hw] = src[b * kCHW + (cT * 32 + cl) * 1024 + hwT * 32 + hw];
    }
    __syncthreads();
    int tokl = tid >> 3, c4 = tid & 7;
    float* dst = g_alimb +
        ((size_t)tensor * 65536 + b * 1024 + hwT * 32 + tokl) * 256 + cT * 32;
#pragma unroll
    for (int j = 0; j < 4; j++) {
        int kk = c4 * 4 + j;
        dst[kperm(kk)] = to_tf32(s[kk][tokl]);
    }
}

// ---------------------------------------------------------------------------
__device__ __forceinline__ void issue_copy(uint32_t sb, int tid, int t,
                                           int tensor, int tloc) {
    const int pass = t >> 3, chunk = t & 7;
    const uint32_t dB = sb + (t % 3) * BUF;
#pragma unroll
    for (int u = 0; u < 4; u++) {                       // A: 1024 f4
        int i = tid + u * 256;
        int tok = i >> 3, k4 = i & 7;
        const float* src = g_alimb +
            ((size_t)tensor * 65536 + tloc + tok) * 256 + chunk * 32 + k4 * 4;
        cp16(dB + tok * 144 + k4 * 16, src);
    }
#pragma unroll
    for (int u = 0; u < 4; u++) {                       // B: 1024 f4
        int i = tid + u * 256;
        int code = i >> 3, k4 = i & 7;
        const float* src = g_blimb +
            ((size_t)(pass * 128 + code)) * 256 + chunk * 32 + k4 * 4;
        cp16(dB + SM_B + code * 144 + k4 * 16, src);
    }
}

// #4 (ncu slot): GEMM + top-2 argmin, LDS.128 fragments, 3-stage pipeline.
__global__ void __launch_bounds__(256, 2)
argmin_mma_kernel() {
    extern __shared__ char smem[];
    const uint32_t sb = smem_u32(smem);
    const int tid = threadIdx.x, lane = tid & 31, w = tid >> 5;
    const int r0 = lane >> 2, cg = lane & 3;
    const int mw = w & 3, nw = w >> 2;
    const int tensor = blockIdx.x >> 9;
    const int tloc = (blockIdx.x & 511) * 128;

    float sTok[4];
#pragma unroll
    for (int s = 0; s < 4; s++)
        sTok[s] = g_tokNorm[tensor * kNTok + tloc + mw * 32 + (s >> 1) * 16 + (s & 1) * 8 + r0];

    float rowV = 3.4e38f, rowV2 = 3.4e38f; int rowI = 0;
    float acc[2][8][4];

    issue_copy(sb, tid, 0, tensor, tloc); CP_COMMIT();
    issue_copy(sb, tid, 1, tensor, tloc); CP_COMMIT();

    for (int t = 0; t < 64; t++) {
        const int pass = t >> 3, chunk = t & 7;
        if (t == 63) CP_WAIT0(); else CP_WAIT1();
        __syncthreads();
        if (t + 2 < 64) { issue_copy(sb, tid, t + 2, tensor, tloc); CP_COMMIT(); }
        if (chunk == 0) {
            if (tid < 128)
                *(float*)(smem + SM_NORM + tid * 4) = g_codeNorm[pass * 128 + tid];
#pragma unroll
            for (int i = 0; i < 2; i++)
#pragma unroll
                for (int j = 0; j < 8; j++)
#pragma unroll
                    for (int q = 0; q < 4; q++) acc[i][j][q] = 0.f;
        }
        const char* bp = smem + (t % 3) * BUF;
#pragma unroll
        for (int hh = 0; hh < 2; hh++) {                 // k-step halves
            // A fragments: per mtile, rows r0 and r0+8, one float4 each
            float4 fa[2][2];
#pragma unroll
            for (int i = 0; i < 2; i++) {
                int rowA = mw * 32 + i * 16 + r0;
                fa[i][0] = *(const float4*)(bp + rowA * 144 + cg * 32 + hh * 16);
                fa[i][1] = *(const float4*)(bp + (rowA + 8) * 144 + cg * 32 + hh * 16);
            }
#pragma unroll
            for (int j = 0; j < 8; j++) {
                float4 fb = *(const float4*)(bp + SM_B +
                    (nw * 64 + j * 8 + r0) * 144 + cg * 32 + hh * 16);
#pragma unroll
                for (int ls = 0; ls < 2; ls++) {
                    uint32_t b0 = __float_as_uint(((const float*)&fb)[ls * 2 + 0]);
                    uint32_t b1 = __float_as_uint(((const float*)&fb)[ls * 2 + 1]);
#pragma unroll
                    for (int i = 0; i < 2; i++) {
                        uint32_t a0 = __float_as_uint(((const float*)&fa[i][0])[ls * 2 + 0]);
                        uint32_t a2 = __float_as_uint(((const float*)&fa[i][0])[ls * 2 + 1]);
                        uint32_t a1 = __float_as_uint(((const float*)&fa[i][1])[ls * 2 + 0]);
                        uint32_t a3 = __float_as_uint(((const float*)&fa[i][1])[ls * 2 + 1]);
                        MMA(acc[i][j], a0, a1, a2, a3, b0, b1);
                    }
                }
            }
        }
        if (chunk == 7) {
#pragma unroll
            for (int i = 0; i < 2; i++)
#pragma unroll
                for (int p = 0; p < 2; p++) {
                    float v1 = 3.4e38f, v2 = 3.4e38f; int i1 = 0;
#pragma unroll
                    for (int j = 0; j < 8; j++)
#pragma unroll
                        for (int q = 0; q < 2; q++) {
                            int cl = nw * 64 + j * 8 + cg * 2 + q;
                            float n = *(const float*)(smem + SM_NORM + cl * 4);
                            float d = __fadd_rn(__fadd_rn(sTok[i * 2 + p], n),
                                                -__fmul_rn(2.0f, acc[i][j][p * 2 + q]));
                            if (d < v1) { v2 = v1; v1 = d; i1 = cl; }
                            else if (d < v2) v2 = d;
                        }
                    for (int off = 1; off < 4; off <<= 1) {
                        float ov1 = __shfl_xor_sync(0xffffffffu, v1, off);
                        float ov2 = __shfl_xor_sync(0xffffffffu, v2, off);
                        int   oi1 = __shfl_xor_sync(0xffffffffu, i1, off);
                        if (ov1 < v1 || (ov1 == v1 && oi1 < i1)) {
                            v2 = fminf(v1, ov2); v1 = ov1; i1 = oi1;
                        } else {
                            v2 = fminf(v2, ov1);
                        }
                    }
                    if (cg == 0) {
                        int row = mw * 32 + i * 16 + p * 8 + r0;
                        *(float*)(smem + SM_RV  + (nw * 128 + row) * 4) = v1;
                        *(int*)  (smem + SM_RI  + (nw * 128 + row) * 4) = i1;
                        *(float*)(smem + SM_RV2 + (nw * 128 + row) * 4) = v2;
                    }
                }
            __syncthreads();
            if (tid < 128) {
                float a1 = *(float*)(smem + SM_RV + tid * 4);
                int   ai = *(int*)  (smem + SM_RI + tid * 4);
                float a2 = *(float*)(smem + SM_RV2 + tid * 4);
                float b1 = *(float*)(smem + SM_RV + (128 + tid) * 4);
                int   bi = *(int*)  (smem + SM_RI + (128 + tid) * 4);
                float b2 = *(float*)(smem + SM_RV2 + (128 + tid) * 4);
                if (b1 < a1) { a2 = fminf(a1, b2); a1 = b1; ai = bi; }
                else         { a2 = fminf(a2, b1); }
                if (a1 < rowV) { rowV2 = fminf(rowV, a2); rowV = a1; rowI = pass * 128 + ai; }
                else           { rowV2 = fminf(rowV2, a1); }
            }
        }
    }
    if (tid < 128) {
        int t = tensor * kNTok + tloc + tid;
        g_idx[t] = rowI;
        if (rowV2 - rowV < kMargin) {
            int slot = atomicAdd(&g_flagCount, 1);
            if (slot < kFlagCap) {
                g_flagList[slot] = t;
                g_refKey[slot] = 0xFFFFFFFFFFFFFFFFull;
            }
        }
    }
}

// ---------------------------------------------------------------------------
// #5: batched exact re-check; work item = (batch of 16 tokens, quarter of codes).
// Merged via atomicMin on (d_bits<<32)|code — order-independent, tie-break = low idx.
__global__ void __launch_bounds__(256)
refine_kernel(const float* __restrict__ z, const float* __restrict__ gt,
              const float* __restrict__ cb) {
    __shared__ float xs[16][260];
    __shared__ float dm[16][257];
    __shared__ float sn[16];
    __shared__ int   st[16];
    __shared__ int   sf[16];
    int nf = g_flagCount; if (nf > kFlagCap) nf = kFlagCap;
    int nItems = ((nf + 15) >> 4) * 4;
    const int tid = threadIdx.x, lane = tid & 31, w = tid >> 5;
    for (int item = blockIdx.x; item < nItems; item += gridDim.x) {
        int b = item >> 2, s = item & 3;
        __syncthreads();
#pragma unroll
        for (int ii = 0; ii < 2; ii++) {
            int i = w * 2 + ii;
            int slot = b * 16 + i;
            int ok = slot < nf;
            int tk = g_flagList[ok ? slot : nf - 1];
            int tensor = tk >> 16, tl = tk & 65535;
            const float* src = (tensor ? gt : z) + (tl >> 10) * kCHW + (tl & 1023);
            for (int k = lane; k < 256; k += 32) xs[i][k] = src[k * 1024];
            if (lane == 0) { st[i] = ok ? tk : -1; sf[i] = slot; sn[i] = g_tokNorm[tk]; }
        }
        __syncthreads();
        const float4* e4 = (const float4*)(cb + (s * 256 + tid) * 256);
        float acc[16];
#pragma unroll
        for (int i = 0; i < 16; i++) acc[i] = 0.f;
        float4 ev = e4[0];
        for (int k4 = 0; k4 < 64; k4++) {
            float4 evn = e4[(k4 + 1) & 63];     // prefetch (wraps harmlessly at end)
#pragma unroll
            for (int i = 0; i < 16; i++) {
                float4 xv = *(const float4*)&xs[i][k4 * 4];
                acc[i] = fmaf(xv.x, ev.x, acc[i]);
                acc[i] = fmaf(xv.y, ev.y, acc[i]);
                acc[i] = fmaf(xv.z, ev.z, acc[i]);
                acc[i] = fmaf(xv.w, ev.w, acc[i]);
            }
            ev = evn;
        }
        float cn = g_codeNorm[s * 256 + tid];
#pragma unroll
        for (int i = 0; i < 16; i++)
            dm[i][tid] = __fadd_rn(__fadd_rn(sn[i], cn),
                                   -__fmul_rn(2.0f, acc[i]));
        __syncthreads();
#pragma unroll
        for (int ii = 0; ii < 2; ii++) {
            int i = w * 2 + ii;
            float v = 3.4e38f; int vi = 0x7fffffff;
            for (int jj = lane; jj < 256; jj += 32) {
                float d = dm[i][jj]; int ci = s * 256 + jj;
                if (d < v || (d == v && ci < vi)) { v = d; vi = ci; }
            }
            for (int off = 16; off > 0; off >>= 1) {
                float ovv = __shfl_xor_sync(0xffffffffu, v, off);
                int   ovi = __shfl_xor_sync(0xffffffffu, vi, off);
                if (ovv < v || (ovv == v && ovi < vi)) { v = ovv; vi = ovi; }
            }
            if (lane == 0 && st[i] >= 0) {
                unsigned long long key =
                    ((unsigned long long)__float_as_uint(v) << 32) | (unsigned)vi;
                atomicMin(&g_refKey[sf[i]], key);
            }
        }
    }
}

// #6: commit refined winners.
__global__ void refine_commit_kernel() {
    int f = blockIdx.x * blockDim.x + threadIdx.x;
    int nf = g_flagCount; if (nf > kFlagCap) nf = kFlagCap;
    if (f < nf)
        g_idx[g_flagList[f]] = (int)(unsigned)(g_refKey[f] & 0xFFFFFFFFull);
}

// ---------------------------------------------------------------------------
__global__ void write_zq_kernel(const float* __restrict__ cb,
                                float* __restrict__ out) {
    int i = blockIdx.x * blockDim.x + threadIdx.x;
    int t = i >> 6, cq = i & 63;
    int idx = g_idx[t];
    ((float4*)out)[i] = ((const float4*)(cb + idx * kC))[cq];
}

__global__ void write_idx_kernel(float* __restrict__ out) {
    int t = blockIdx.x * blockDim.x + threadIdx.x;
    if (t >= kNTok) return;
    out[kOffIdxG + t] = (float)g_idx[kNTok + t];
    out[kOffIdxZ + t] = (float)g_idx[t];
}

__global__ void cosine_kernel(const float* __restrict__ cb,
                              float* __restrict__ out) {
    int bw = blockIdx.x;
    int b = bw >> 5, w = bw & 31;
    int c = threadIdx.x;
    __shared__ int sig[32], siz[32];
    if (threadIdx.x < 32) {
        int h = threadIdx.x;
        int t = b * 1024 + h * 32 + w;
        sig[h] = g_idx[kNTok + t];
        siz[h] = g_idx[t];
    }
    __syncthreads();
    float num = 0.f, ng = 0.f, nz = 0.f;
    for (int h = 0; h < 32; ++h) {
        float g = cb[sig[h] * kC + c];
        float q = cb[siz[h] * kC + c];
        num = fmaf(g, q, num);
        ng  = fmaf(g, g, ng);
        nz  = fmaf(q, q, nz);
    }
    float den = fmaxf(sqrtf(ng), 1e-8f) * fmaxf(sqrtf(nz), 1e-8f);
    out[kOffCos + bw * kC + c] = num / den;
}

// ---------------------------------------------------------------------------
extern "C" void kernel_launch(void* const* d_in, const int* in_sizes, int n_in,
                              void* d_out, int out_size) {
    const float* z  = (const float*)d_in[0];
    const float* gt = (const float*)d_in[1];
    const float* cb = (const float*)d_in[2];
    float* out = (float*)d_out;
    (void)in_sizes; (void)n_in; (void)out_size;

    cudaFuncSetAttribute(argmin_mma_kernel,
                         cudaFuncAttributeMaxDynamicSharedMemorySize, SMEM_BYTES);

    prep_cb_kernel<<<4, 256>>>(cb);                              // launch 1
    prep_tok_kernel<<<512, 256>>>(z, gt);                        // launch 2
    alimb_kernel<<<32768, 256>>>(z, gt);                         // launch 3
    argmin_mma_kernel<<<1024, 256, SMEM_BYTES>>>();              // launch 4 (ncu)
    refine_kernel<<<2048, 256>>>(z, gt, cb);                     // launch 5
    refine_commit_kernel<<<kFlagCap / 256, 256>>>();             // launch 6
    write_zq_kernel<<<(kZQ / 4) / 256, 256>>>(cb, out);          // launch 7
    write_idx_kernel<<<(kNTok + 255) / 256, 256>>>(out);         // launch 8
    cosine_kernel<<<64 * 32, 256>>>(cb, out);                    // launch 9
}

// round 10
// speedup vs baseline: 1.1059x; 1.1059x over previous
#include <cuda_runtime.h>
#include <cstdint>

// ---------------------------------------------------------------------------
// VQ nearest-code quantization + cosine score — 1xTF32 mma.sync + exact refine.
// R10: R8's proven argmin/staging + R9's parallel atomicMin refine.
// ---------------------------------------------------------------------------

namespace {
constexpr int kC    = 256;
constexpr int kNE   = 1024;
constexpr int kCHW  = 256 * 1024;
constexpr int kNTok = 64 * 1024;
constexpr int kZQ   = kNTok * kC;
constexpr int kCOS  = 64 * 32 * 256;
constexpr int kOffCos  = kZQ;
constexpr int kOffIdxG = kZQ + kCOS;
constexpr int kOffIdxZ = kOffIdxG + kNTok;
constexpr int kFlagCap = 2 * kNTok;
constexpr float kMargin = 2e-3f;          // ~10 sigma of tf32(rna) dot error
}

__device__ float g_codeNorm[kNE];
__device__ float g_tokNorm[2 * kNTok];
__device__ int   g_idx[2 * kNTok];
__device__ float g_blimb[1024 * 256];             // tf32-rounded codebook (k-major)
__device__ float g_alimb[2ll * 65536 * 256];      // tf32-rounded tokens, token-major
__device__ int   g_flagCount;
__device__ int   g_flagList[kFlagCap];
__device__ unsigned long long g_refKey[kFlagCap];

// ------------------------------ helpers ------------------------------------
__device__ __forceinline__ uint32_t smem_u32(const void* p) {
    uint32_t a;
    asm("{ .reg .u64 t; cvta.to.shared.u64 t, %1; cvt.u32.u64 %0, t; }"
        : "=r"(a) : "l"(p));
    return a;
}
__device__ __forceinline__ float to_tf32(float x) {
    float r; asm("cvt.rna.tf32.f32 %0, %1;" : "=f"(r) : "f"(x)); return r;
}
__device__ __forceinline__ void cp16(uint32_t dst, const float* src) {
    asm volatile("cp.async.cg.shared.global [%0], [%1], 16;"
                 :: "r"(dst), "l"(src) : "memory");
}
#define CP_COMMIT() asm volatile("cp.async.commit_group;" ::: "memory")
#define CP_WAIT1()  asm volatile("cp.async.wait_group 1;" ::: "memory")
#define CP_WAIT0()  asm volatile("cp.async.wait_group 0;" ::: "memory")

#define MMA(d, a, b0, b1) \
    asm volatile("mma.sync.aligned.m16n8k8.row.col.f32.tf32.tf32.f32 " \
        "{%0,%1,%2,%3}, {%4,%5,%6,%7}, {%8,%9}, {%0,%1,%2,%3};" \
        : "+f"((d)[0]), "+f"((d)[1]), "+f"((d)[2]), "+f"((d)[3]) \
        : "r"((a)[0]), "r"((a)[1]), "r"((a)[2]), "r"((a)[3]), "r"(b0), "r"(b1))

// SMEM: buffer b (b=0..2) at b*36864: A [128][36]f @0, B [128][36]f @18432
#define BUF     36864
#define SM_B    18432
#define SM_NORM 110592
#define SM_RV   111104
#define SM_RI   112128
#define SM_RV2  113152
#define SMEM_BYTES 114176

// ---------------------------------------------------------------------------
// #1: codebook norms + tf32 rounding; flag reset.
__global__ void prep_cb_kernel(const float* __restrict__ cb) {
    int j = blockIdx.x * blockDim.x + threadIdx.x;
    if (j == 0) g_flagCount = 0;
    if (j >= kNE) return;
    const float* r = cb + j * kC;
    float s = 0.f;
    for (int c = 0; c < kC; ++c) {
        float v = r[c];
        s = fmaf(v, v, s);
        g_blimb[j * kC + c] = to_tf32(v);
    }
    g_codeNorm[j] = s;
}

// #2: exact token norms (ascending-c fmaf chain, matches refine).
__global__ void prep_tok_kernel(const float* __restrict__ z,
                                const float* __restrict__ gt) {
    int t = blockIdx.x * blockDim.x + threadIdx.x;
    if (t >= 2 * kNTok) return;
    const float* src = (t < kNTok) ? z : gt;
    int tl = t & (kNTok - 1);
    const float* p = src + (tl >> 10) * kCHW + (tl & 1023);
    float s = 0.f;
    for (int c = 0; c < kC; ++c) { float a = p[c * 1024]; s = fmaf(a, a, s); }
    g_tokNorm[t] = s;
}

// #3: transpose+round z/gt: g_alimb[tensor][tok][k]  (float4 stores)
__global__ void alimb_kernel(const float* __restrict__ z,
                             const float* __restrict__ gt) {
    __shared__ float s[32][33];
    int blk = blockIdx.x;                 // 2 * 64 * 32 * 8
    int tensor = blk >> 14;
    int b   = (blk >> 8) & 63;
    int hwT = (blk >> 3) & 31;
    int cT  = blk & 7;
    const float* src = tensor ? gt : z;
    int tid = threadIdx.x;
#pragma unroll
    for (int u = 0; u < 4; u++) {
        int cl = (tid >> 5) + u * 8, hw = tid & 31;
        s[cl][hw] = src[b * kCHW + (cT * 32 + cl) * 1024 + hwT * 32 + hw];
    }
    __syncthreads();
    int tokl = tid >> 3, c4 = tid & 7;
    float4 hi;
    hi.x = to_tf32(s[c4 * 4 + 0][tokl]);
    hi.y = to_tf32(s[c4 * 4 + 1][tokl]);
    hi.z = to_tf32(s[c4 * 4 + 2][tokl]);
    hi.w = to_tf32(s[c4 * 4 + 3][tokl]);
    size_t base = ((size_t)tensor * 65536 + b * 1024 + hwT * 32 + tokl) * 256
                + cT * 32 + c4 * 4;
    *(float4*)(g_alimb + base) = hi;
}

// ---------------------------------------------------------------------------
__device__ __forceinline__ void issue_copy(uint32_t sb, int tid, int t,
                                           int tensor, int tloc) {
    const int pass = t >> 3, chunk = t & 7;
    const uint32_t dB = sb + (t % 3) * BUF;
#pragma unroll
    for (int u = 0; u < 4; u++) {                       // A: 1024 f4
        int i = tid + u * 256;
        int tok = i >> 3, k4 = i & 7;
        const float* src = g_alimb +
            ((size_t)tensor * 65536 + tloc + tok) * 256 + chunk * 32 + k4 * 4;
        cp16(dB + tok * 144 + k4 * 16, src);
    }
#pragma unroll
    for (int u = 0; u < 4; u++) {                       // B: 1024 f4
        int i = tid + u * 256;
        int code = i >> 3, k4 = i & 7;
        const float* src = g_blimb +
            ((size_t)(pass * 128 + code)) * 256 + chunk * 32 + k4 * 4;
        cp16(dB + SM_B + code * 144 + k4 * 16, src);
    }
}

// #4 (ncu slot): GEMM + top-2 argmin, 3-stage cp.async pipeline (R8 mainloop).
__global__ void __launch_bounds__(256, 2)
argmin_mma_kernel() {
    extern __shared__ char smem[];
    const uint32_t sb = smem_u32(smem);
    const int tid = threadIdx.x, lane = tid & 31, w = tid >> 5;
    const int r0 = lane >> 2, cg = lane & 3;
    const int mw = w & 3, nw = w >> 2;                  // nw in 0..1
    const int tensor = blockIdx.x >> 9;
    const int tloc = (blockIdx.x & 511) * 128;

    float sTok[4];
#pragma unroll
    for (int s = 0; s < 4; s++)
        sTok[s] = g_tokNorm[tensor * kNTok + tloc + mw * 32 + (s >> 1) * 16 + (s & 1) * 8 + r0];

    float rowV = 3.4e38f, rowV2 = 3.4e38f; int rowI = 0;
    float acc[2][8][4];

    issue_copy(sb, tid, 0, tensor, tloc); CP_COMMIT();
    issue_copy(sb, tid, 1, tensor, tloc); CP_COMMIT();

    for (int t = 0; t < 64; t++) {
        const int pass = t >> 3, chunk = t & 7;
        if (t == 63) CP_WAIT0(); else CP_WAIT1();
        __syncthreads();
        if (t + 2 < 64) { issue_copy(sb, tid, t + 2, tensor, tloc); CP_COMMIT(); }
        if (chunk == 0) {
            if (tid < 128)
                *(float*)(smem + SM_NORM + tid * 4) = g_codeNorm[pass * 128 + tid];
#pragma unroll
            for (int i = 0; i < 2; i++)
#pragma unroll
                for (int j = 0; j < 8; j++)
#pragma unroll
                    for (int q = 0; q < 4; q++) acc[i][j][q] = 0.f;
        }
        const char* bp = smem + (t % 3) * BUF;
#pragma unroll
        for (int ks = 0; ks < 4; ks++) {
            uint32_t aH[2][4];
#pragma unroll
            for (int i = 0; i < 2; i++) {
                const char* ab = bp + (mw * 32 + i * 16 + r0) * 144 + (ks * 8 + cg) * 4;
                aH[i][0] = *(const uint32_t*)ab;
                aH[i][1] = *(const uint32_t*)(ab + 8 * 144);
                aH[i][2] = *(const uint32_t*)(ab + 16);
                aH[i][3] = *(const uint32_t*)(ab + 8 * 144 + 16);
            }
#pragma unroll
            for (int j = 0; j < 8; j++) {
                const char* bb = bp + SM_B + (nw * 64 + j * 8 + r0) * 144 + (ks * 8 + cg) * 4;
                uint32_t bh0 = *(const uint32_t*)bb;
                uint32_t bh1 = *(const uint32_t*)(bb + 16);
                MMA(acc[0][j], aH[0], bh0, bh1);
                MMA(acc[1][j], aH[1], bh0, bh1);
            }
        }
        if (chunk == 7) {
#pragma unroll
            for (int i = 0; i < 2; i++)
#pragma unroll
                for (int p = 0; p < 2; p++) {
                    float v1 = 3.4e38f, v2 = 3.4e38f; int i1 = 0;
#pragma unroll
                    for (int j = 0; j < 8; j++)
#pragma unroll
                        for (int q = 0; q < 2; q++) {
                            int cl = nw * 64 + j * 8 + cg * 2 + q;
                            float n = *(const float*)(smem + SM_NORM + cl * 4);
                            float d = __fadd_rn(__fadd_rn(sTok[i * 2 + p], n),
                                                -__fmul_rn(2.0f, acc[i][j][p * 2 + q]));
                            if (d < v1) { v2 = v1; v1 = d; i1 = cl; }
                            else if (d < v2) v2 = d;
                        }
                    for (int off = 1; off < 4; off <<= 1) {
                        float ov1 = __shfl_xor_sync(0xffffffffu, v1, off);
                        float ov2 = __shfl_xor_sync(0xffffffffu, v2, off);
                        int   oi1 = __shfl_xor_sync(0xffffffffu, i1, off);
                        if (ov1 < v1 || (ov1 == v1 && oi1 < i1)) {
                            v2 = fminf(v1, ov2); v1 = ov1; i1 = oi1;
                        } else {
                            v2 = fminf(v2, ov1);
                        }
                    }
                    if (cg == 0) {
                        int row = mw * 32 + i * 16 + p * 8 + r0;
                        *(float*)(smem + SM_RV  + (nw * 128 + row) * 4) = v1;
                        *(int*)  (smem + SM_RI  + (nw * 128 + row) * 4) = i1;
                        *(float*)(smem + SM_RV2 + (nw * 128 + row) * 4) = v2;
                    }
                }
            __syncthreads();
            if (tid < 128) {
                float a1 = *(float*)(smem + SM_RV + tid * 4);
                int   ai = *(int*)  (smem + SM_RI + tid * 4);
                float a2 = *(float*)(smem + SM_RV2 + tid * 4);
                float b1 = *(float*)(smem + SM_RV + (128 + tid) * 4);
                int   bi = *(int*)  (smem + SM_RI + (128 + tid) * 4);
                float b2 = *(float*)(smem + SM_RV2 + (128 + tid) * 4);
                if (b1 < a1) { a2 = fminf(a1, b2); a1 = b1; ai = bi; }
                else         { a2 = fminf(a2, b1); }
                if (a1 < rowV) { rowV2 = fminf(rowV, a2); rowV = a1; rowI = pass * 128 + ai; }
                else           { rowV2 = fminf(rowV2, a1); }
            }
        }
    }
    if (tid < 128) {
        int t = tensor * kNTok + tloc + tid;
        g_idx[t] = rowI;
        if (rowV2 - rowV < kMargin) {
            int slot = atomicAdd(&g_flagCount, 1);
            if (slot < kFlagCap) {
                g_flagList[slot] = t;
                g_refKey[slot] = 0xFFFFFFFFFFFFFFFFull;
            }
        }
    }
}

// ---------------------------------------------------------------------------
// #5: batched exact re-check; work item = (batch of 16 tokens, quarter of codes).
// Merge via atomicMin on (d_bits<<32)|code — order-independent, low-idx tie-break.
__global__ void __launch_bounds__(256)
refine_kernel(const float* __restrict__ z, const float* __restrict__ gt,
              const float* __restrict__ cb) {
    __shared__ float xs[16][260];
    __shared__ float dm[16][257];
    __shared__ float sn[16];
    __shared__ int   st[16];
    __shared__ int   sf[16];
    int nf = g_flagCount; if (nf > kFlagCap) nf = kFlagCap;
    int nItems = ((nf + 15) >> 4) * 4;
    const int tid = threadIdx.x, lane = tid & 31, w = tid >> 5;
    for (int item = blockIdx.x; item < nItems; item += gridDim.x) {
        int b = item >> 2, s = item & 3;
        __syncthreads();
#pragma unroll
        for (int ii = 0; ii < 2; ii++) {
            int i = w * 2 + ii;
            int slot = b * 16 + i;
            int ok = slot < nf;
            int tk = g_flagList[ok ? slot : nf - 1];
            int tensor = tk >> 16, tl = tk & 65535;
            const float* src = (tensor ? gt : z) + (tl >> 10) * kCHW + (tl & 1023);
            for (int k = lane; k < 256; k += 32) xs[i][k] = src[k * 1024];
            if (lane == 0) { st[i] = ok ? tk : -1; sf[i] = slot; sn[i] = g_tokNorm[tk]; }
        }
        __syncthreads();
        const float4* e4 = (const float4*)(cb + (s * 256 + tid) * 256);
        float acc[16];
#pragma unroll
        for (int i = 0; i < 16; i++) acc[i] = 0.f;
        float4 ev = e4[0];
        for (int k4 = 0; k4 < 64; k4++) {
            float4 evn = e4[(k4 + 1) & 63];
#pragma unroll
            for (int i = 0; i < 16; i++) {
                float4 xv = *(const float4*)&xs[i][k4 * 4];
                acc[i] = fmaf(xv.x, ev.x, acc[i]);
                acc[i] = fmaf(xv.y, ev.y, acc[i]);
                acc[i] = fmaf(xv.z, ev.z, acc[i]);
                acc[i] = fmaf(xv.w, ev.w, acc[i]);
            }
            ev = evn;
        }
        float cn = g_codeNorm[s * 256 + tid];
#pragma unroll
        for (int i = 0; i < 16; i++)
            dm[i][tid] = __fadd_rn(__fadd_rn(sn[i], cn),
                                   -__fmul_rn(2.0f, acc[i]));
        __syncthreads();
#pragma unroll
        for (int ii = 0; ii < 2; ii++) {
            int i = w * 2 + ii;
            float v = 3.4e38f; int vi = 0x7fffffff;
            for (int jj = lane; jj < 256; jj += 32) {
                float d = dm[i][jj]; int ci = s * 256 + jj;
                if (d < v || (d == v && ci < vi)) { v = d; vi = ci; }
            }
            for (int off = 16; off > 0; off >>= 1) {
                float ovv = __shfl_xor_sync(0xffffffffu, v, off);
                int   ovi = __shfl_xor_sync(0xffffffffu, vi, off);
                if (ovv < v || (ovv == v && ovi < vi)) { v = ovv; vi = ovi; }
            }
            if (lane == 0 && st[i] >= 0) {
                unsigned long long key =
                    ((unsigned long long)__float_as_uint(v) << 32) | (unsigned)vi;
                atomicMin(&g_refKey[sf[i]], key);
            }
        }
    }
}

// #6: commit refined winners.
__global__ void refine_commit_kernel() {
    int f = blockIdx.x * blockDim.x + threadIdx.x;
    int nf = g_flagCount; if (nf > kFlagCap) nf = kFlagCap;
    if (f < nf)
        g_idx[g_flagList[f]] = (int)(unsigned)(g_refKey[f] & 0xFFFFFFFFull);
}

// ---------------------------------------------------------------------------
__global__ void write_zq_kernel(const float* __restrict__ cb,
                                float* __restrict__ out) {
    int i = blockIdx.x * blockDim.x + threadIdx.x;
    int t = i >> 6, cq = i & 63;
    int idx = g_idx[t];
    ((float4*)out)[i] = ((const float4*)(cb + idx * kC))[cq];
}

__global__ void write_idx_kernel(float* __restrict__ out) {
    int t = blockIdx.x * blockDim.x + threadIdx.x;
    if (t >= kNTok) return;
    out[kOffIdxG + t] = (float)g_idx[kNTok + t];
    out[kOffIdxZ + t] = (float)g_idx[t];
}

__global__ void cosine_kernel(const float* __restrict__ cb,
                              float* __restrict__ out) {
    int bw = blockIdx.x;
    int b = bw >> 5, w = bw & 31;
    int c = threadIdx.x;
    __shared__ int sig[32], siz[32];
    if (threadIdx.x < 32) {
        int h = threadIdx.x;
        int t = b * 1024 + h * 32 + w;
        sig[h] = g_idx[kNTok + t];
        siz[h] = g_idx[t];
    }
    __syncthreads();
    float num = 0.f, ng = 0.f, nz = 0.f;
    for (int h = 0; h < 32; ++h) {
        float g = cb[sig[h] * kC + c];
        float q = cb[siz[h] * kC + c];
        num = fmaf(g, q, num);
        ng  = fmaf(g, g, ng);
        nz  = fmaf(q, q, nz);
    }
    float den = fmaxf(sqrtf(ng), 1e-8f) * fmaxf(sqrtf(nz), 1e-8f);
    out[kOffCos + bw * kC + c] = num / den;
}

// ---------------------------------------------------------------------------
extern "C" void kernel_launch(void* const* d_in, const int* in_sizes, int n_in,
                              void* d_out, int out_size) {
    const float* z  = (const float*)d_in[0];
    const float* gt = (const float*)d_in[1];
    const float* cb = (const float*)d_in[2];
    float* out = (float*)d_out;
    (void)in_sizes; (void)n_in; (void)out_size;

    cudaFuncSetAttribute(argmin_mma_kernel,
                         cudaFuncAttributeMaxDynamicSharedMemorySize, SMEM_BYTES);

    prep_cb_kernel<<<4, 256>>>(cb);                              // launch 1
    prep_tok_kernel<<<512, 256>>>(z, gt);                        // launch 2
    alimb_kernel<<<32768, 256>>>(z, gt);                         // launch 3
    argmin_mma_kernel<<<1024, 256, SMEM_BYTES>>>();              // launch 4 (ncu)
    refine_kernel<<<2048, 256>>>(z, gt, cb);                     // launch 5
    refine_commit_kernel<<<kFlagCap / 256, 256>>>();             // launch 6
    write_zq_kernel<<<(kZQ / 4) / 256, 256>>>(cb, out);          // launch 7
    write_idx_kernel<<<(kNTok + 255) / 256, 256>>>(out);         // launch 8
    cosine_kernel<<<64 * 32, 256>>>(cb, out);                    // launch 9
}